// round 1
// baseline (speedup 1.0000x reference)
#include <cuda_runtime.h>

// ---------------------------------------------------------------------------
// Seq2seq LSTM (2-layer encoder T=512, B=256, H=256; decoder S*B=4096, 64 steps)
// Strategy: ONE persistent kernel, grid = 148 CTAs (1 per SM, all co-resident),
// software grid barrier between dependent layer-steps. Each layer-step is a
// smem-tiled GEMM gates[N x 1024] = h[N x 256] @ W^T (+ optional second GEMM
// for layer-1 input path, + rank-1 input term for layer-0), fused with the
// LSTM gate elementwise update. Inner GEMM uses transposed, k-paired smem
// layouts so the hot loop is LDS.128 + packed fma.rn.f32x2 (FFMA2) -> fp32x2
// FMA-pipe bound.
// ---------------------------------------------------------------------------

#define HID   256
#define BATCH 256
#define TLEN  512
#define NS    16
#define SBAT  (NS * BATCH)   // 4096
#define HOR   64
#define GRID  148
#define NTHR  256

// ---------------- device scratch (no allocation allowed) -------------------
__device__ float g_eh0[2][BATCH * HID];
__device__ float g_ec0[BATCH * HID];
__device__ float g_eh1[2][BATCH * HID];
__device__ float g_ec1[BATCH * HID];

__device__ float g_dh0[2][SBAT * HID];
__device__ float g_dc0[SBAT * HID];
__device__ float g_dh1[2][SBAT * HID];
__device__ float g_dc1[SBAT * HID];
__device__ float g_dinp[SBAT];

__device__ unsigned g_cnt = 0;
__device__ volatile unsigned g_gen = 0;

// ---------------- grid-wide barrier (all CTAs resident) --------------------
__device__ __forceinline__ void gsync() {
    __syncthreads();
    if (threadIdx.x == 0) {
        __threadfence();
        unsigned old = g_gen;
        unsigned arrived = atomicAdd(&g_cnt, 1u);
        if (arrived == gridDim.x - 1) {
            g_cnt = 0;
            __threadfence();
            g_gen = old + 1u;
        } else {
            while (g_gen == old) { }
            __threadfence();
        }
    }
    __syncthreads();
}

// ---------------- packed f32x2 FMA ------------------------------------------
union F2U { float2 f; unsigned long long u; };

__device__ __forceinline__ float2 ffma2(float2 a, float2 b, float2 c) {
    F2U ua, ub, uc;
    ua.f = a; ub.f = b; uc.f = c;
    asm("fma.rn.f32x2 %0, %1, %2, %0;" : "+l"(uc.u) : "l"(ua.u), "l"(ub.u));
    return uc.f;
}

__device__ __forceinline__ float sigm(float x) {
    return 1.0f / (1.0f + expf(-x));
}

// ---------------------------------------------------------------------------
// One [TB x TC] tile of a fused LSTM layer step.
//   gates[b0..b0+TB, cols] = A1 @ W1^T  (+ A2 @ W2^T)  (+ inp[b]*wih[g]) + bias
// cols map hidden indices j0..j0+TJ for all 4 gates (i,f,g,o).
// Then c/h update for the (b, j) elements this tile owns.
// smem layouts (transposed + k-paired for FFMA2):
//   As2[k2][row]  : float2 = (A[row][2k2], A[row][2k2+1]),  row-stride TB+2
//   Ws2[k2][col]  : same for selected W rows,               col-stride TC+2
// ---------------------------------------------------------------------------
template<int TB, int TC>
__device__ void lstm_tile(char* smem, int b0, int j0,
                          const float* __restrict__ A1, const float* __restrict__ W1,
                          const float* __restrict__ A2, const float* __restrict__ W2,
                          const float* __restrict__ inp, int inp_stride,
                          const float* __restrict__ wih,
                          const float* __restrict__ bias,
                          float* __restrict__ Cst, float* __restrict__ Hout)
{
    constexpr int TJ  = TC / 4;
    constexpr int RB  = TB / 16;
    constexpr int RC  = TC / 16;
    constexpr int TBP = TB + 2;
    constexpr int TCP = TC + 2;

    float2* As2 = reinterpret_cast<float2*>(smem);
    float2* Ws2 = reinterpret_cast<float2*>(smem + 128 * TBP * 8);
    float*  gsm = reinterpret_cast<float*>(smem + 128 * TBP * 8 + 128 * TCP * 8);

    const int tid = threadIdx.x;
    const int ty = tid >> 4;   // 0..15 -> rows ty*RB..
    const int tx = tid & 15;   // 0..15 -> cols tx*RC..

    float2 acc[RB][RC];
#pragma unroll
    for (int r = 0; r < RB; ++r)
#pragma unroll
        for (int c = 0; c < RC; ++c) acc[r][c] = make_float2(0.f, 0.f);

    const float* Acur = A1;
    const float* Wcur = W1;

#pragma unroll 1
    for (int pass = 0; pass < 2; ++pass) {
        if (pass == 1) {
            if (A2 == nullptr) break;
            __syncthreads();      // everyone done reading smem from pass 0
            Acur = A2; Wcur = W2;
        }
        // ---- load A tile, transposed + k-paired ----
        for (int idx = tid; idx < TB * 64; idx += NTHR) {
            int r  = idx >> 6;
            int kq = idx & 63;
            float4 v = *reinterpret_cast<const float4*>(
                Acur + (size_t)(b0 + r) * HID + kq * 4);
            As2[(kq * 2)     * TBP + r] = make_float2(v.x, v.y);
            As2[(kq * 2 + 1) * TBP + r] = make_float2(v.z, v.w);
        }
        // ---- load W tile (selected gate rows), transposed + k-paired ----
        for (int idx = tid; idx < TC * 64; idx += NTHR) {
            int c  = idx >> 6;
            int kq = idx & 63;
            int gate = c / TJ;
            int jj   = c - gate * TJ;
            float4 v = *reinterpret_cast<const float4*>(
                Wcur + (size_t)(gate * HID + j0 + jj) * HID + kq * 4);
            Ws2[(kq * 2)     * TCP + c] = make_float2(v.x, v.y);
            Ws2[(kq * 2 + 1) * TCP + c] = make_float2(v.z, v.w);
        }
        __syncthreads();

        // ---- GEMM: 128 k-pair steps, outer product RB x RC per thread ----
#pragma unroll 4
        for (int k2 = 0; k2 < 128; ++k2) {
            const float4* ap = reinterpret_cast<const float4*>(As2 + k2 * TBP + ty * RB);
            const float4* bp = reinterpret_cast<const float4*>(Ws2 + k2 * TCP + tx * RC);
            float2 a[RB], b[RC];
#pragma unroll
            for (int i = 0; i < RB / 2; ++i) {
                float4 v = ap[i];
                a[2 * i]     = make_float2(v.x, v.y);
                a[2 * i + 1] = make_float2(v.z, v.w);
            }
#pragma unroll
            for (int i = 0; i < RC / 2; ++i) {
                float4 v = bp[i];
                b[2 * i]     = make_float2(v.x, v.y);
                b[2 * i + 1] = make_float2(v.z, v.w);
            }
#pragma unroll
            for (int r = 0; r < RB; ++r)
#pragma unroll
                for (int c = 0; c < RC; ++c)
                    acc[r][c] = ffma2(a[r], b[c], acc[r][c]);
        }
    }

    // ---- epilogue: finish dot (pair-sum), add bias + rank-1 input term ----
#pragma unroll
    for (int r = 0; r < RB; ++r) {
        const int lrow = ty * RB + r;
        float inpv = 0.f;
        if (wih) inpv = inp[(size_t)(b0 + lrow) * inp_stride];
#pragma unroll
        for (int cc = 0; cc < RC; ++cc) {
            int c    = tx * RC + cc;
            int gate = c / TJ;
            int jj   = c - gate * TJ;
            int grow = gate * HID + j0 + jj;
            float v = acc[r][cc].x + acc[r][cc].y + bias[grow];
            if (wih) v += inpv * wih[grow];
            gsm[lrow * (TC + 1) + c] = v;
        }
    }
    __syncthreads();

    // ---- gate update: c_new = sig(f)*c + sig(i)*tanh(g); h = sig(o)*tanh(c) --
    for (int idx = tid; idx < TB * TJ; idx += NTHR) {
        int lrow = idx / TJ;
        int jj   = idx - lrow * TJ;
        int gidx = (b0 + lrow) * HID + (j0 + jj);
        const float* gr = gsm + lrow * (TC + 1);
        float iv = gr[jj];
        float fv = gr[TJ + jj];
        float gv = gr[2 * TJ + jj];
        float ov = gr[3 * TJ + jj];
        float cold = Cst[gidx];
        float cn = sigm(fv) * cold + sigm(iv) * tanhf(gv);
        Cst[gidx]  = cn;
        Hout[gidx] = sigm(ov) * tanhf(cn);
    }
    __syncthreads();   // protect gsm/smem before next tile in this CTA
}

// ---------------------------------------------------------------------------
__global__ void __launch_bounds__(NTHR, 1)
lstm_all(const float* __restrict__ x,
         const float* __restrict__ eWih0, const float* __restrict__ eWhh0,
         const float* __restrict__ eb0,
         const float* __restrict__ eWih1, const float* __restrict__ eWhh1,
         const float* __restrict__ eb1,
         const float* __restrict__ dWih0, const float* __restrict__ dWhh0,
         const float* __restrict__ db0,
         const float* __restrict__ dWih1, const float* __restrict__ dWhh1,
         const float* __restrict__ db1,
         const float* __restrict__ outW, const float* __restrict__ outb,
         const float* __restrict__ dinit,
         float* __restrict__ out)
{
    extern __shared__ char smem[];
    const int tid = threadIdx.x;

    // ---- zero-init encoder state (read buffers = index 0) ----
    for (int i = blockIdx.x * NTHR + tid; i < BATCH * HID; i += GRID * NTHR) {
        g_eh0[0][i] = 0.f; g_ec0[i] = 0.f;
        g_eh1[0][i] = 0.f; g_ec1[i] = 0.f;
    }
    gsync();

    // =========================== encoder ===================================
    constexpr int NTE = (BATCH / 32) * (HID / 16);   // 8 * 16 = 128 tiles
    for (int t = 0; t < TLEN; ++t) {
        const int rp = t & 1, wp = rp ^ 1;
        // layer 0: gates = h0 @ Whh0^T + x_t * Wih0 + b0
        for (int tile = blockIdx.x; tile < NTE; tile += GRID) {
            int bt = tile & 7, jt = tile >> 3;
            lstm_tile<32, 64>(smem, bt * 32, jt * 16,
                              g_eh0[rp], eWhh0, nullptr, nullptr,
                              x + t, TLEN, eWih0, eb0,
                              g_ec0, g_eh0[wp]);
        }
        gsync();
        // layer 1: gates = h0_cur @ Wih1^T + h1 @ Whh1^T + b1
        for (int tile = blockIdx.x; tile < NTE; tile += GRID) {
            int bt = tile & 7, jt = tile >> 3;
            lstm_tile<32, 64>(smem, bt * 32, jt * 16,
                              g_eh0[wp], eWih1, g_eh1[rp], eWhh1,
                              nullptr, 0, nullptr, eb1,
                              g_ec1, g_eh1[wp]);
        }
        gsync();
    }

    // ---- decoder init: broadcast final encoder state to S samples ----
    // final encoder buffers are index 0 (512 steps, even)
    for (int i = blockIdx.x * NTHR + tid; i < SBAT * HID; i += GRID * NTHR) {
        int b = (i >> 8) & 255;      // (i/HID) % BATCH
        int k = i & 255;
        int src = b * HID + k;
        g_dh0[0][i] = g_eh0[0][src];
        g_dc0[i]    = g_ec0[src];
        g_dh1[0][i] = g_eh1[0][src];
        g_dc1[i]    = g_ec1[src];
    }
    for (int i = blockIdx.x * NTHR + tid; i < SBAT; i += GRID * NTHR)
        g_dinp[i] = dinit[i];
    gsync();

    // =========================== decoder ===================================
    constexpr int NTD = (SBAT / 64) * (HID / 16);    // 64 * 16 = 1024 tiles
    const int warp = tid >> 5, lane = tid & 31;
    for (int t = 0; t < HOR; ++t) {
        const int rp = t & 1, wp = rp ^ 1;
        for (int tile = blockIdx.x; tile < NTD; tile += GRID) {
            int bt = tile & 63, jt = tile >> 6;
            lstm_tile<64, 64>(smem, bt * 64, jt * 16,
                              g_dh0[rp], dWhh0, nullptr, nullptr,
                              g_dinp, 1, dWih0, db0,
                              g_dc0, g_dh0[wp]);
        }
        gsync();
        for (int tile = blockIdx.x; tile < NTD; tile += GRID) {
            int bt = tile & 63, jt = tile >> 6;
            lstm_tile<64, 64>(smem, bt * 64, jt * 16,
                              g_dh0[wp], dWih1, g_dh1[rp], dWhh1,
                              nullptr, 0, nullptr, db1,
                              g_dc1, g_dh1[wp]);
        }
        gsync();
        // ---- pred = h1 @ outW^T + outb ; feeds next step + output tensor ----
        const float* h1w = g_dh1[wp];
        for (int row = blockIdx.x * 8 + warp; row < SBAT; row += GRID * 8) {
            const float* hr = h1w + (size_t)row * HID;
            float s = 0.f;
#pragma unroll
            for (int kb = 0; kb < 2; ++kb) {
                int kk = kb * 128 + lane * 4;
                float4 hv = *reinterpret_cast<const float4*>(hr + kk);
                float4 wv = *reinterpret_cast<const float4*>(outW + kk);
                s += hv.x * wv.x + hv.y * wv.y + hv.z * wv.z + hv.w * wv.w;
            }
#pragma unroll
            for (int off = 16; off; off >>= 1)
                s += __shfl_xor_sync(0xffffffffu, s, off);
            if (lane == 0) {
                float p = s + outb[0];
                g_dinp[row] = p;
                int b = row & 255, sidx = row >> 8;
                out[(size_t)b * (NS * HOR) + sidx * HOR + t] = p;
            }
        }
        gsync();
    }
}

// ---------------------------------------------------------------------------
extern "C" void kernel_launch(void* const* d_in, const int* in_sizes, int n_in,
                              void* d_out, int out_size)
{
    (void)in_sizes; (void)n_in; (void)out_size;
    const float* x     = (const float*)d_in[0];
    const float* eWih0 = (const float*)d_in[1];
    const float* eWhh0 = (const float*)d_in[2];
    const float* eb0   = (const float*)d_in[3];
    const float* eWih1 = (const float*)d_in[4];
    const float* eWhh1 = (const float*)d_in[5];
    const float* eb1   = (const float*)d_in[6];
    const float* dWih0 = (const float*)d_in[7];
    const float* dWhh0 = (const float*)d_in[8];
    const float* db0   = (const float*)d_in[9];
    const float* dWih1 = (const float*)d_in[10];
    const float* dWhh1 = (const float*)d_in[11];
    const float* db1   = (const float*)d_in[12];
    const float* outW  = (const float*)d_in[13];
    const float* outb  = (const float*)d_in[14];
    const float* dinit = (const float*)d_in[15];
    float* out = (float*)d_out;

    // smem: As2(128*66*8) + Ws2(128*66*8) + gates(64*65*4) = 151808 B
    const int SMEM_BYTES = 128 * 66 * 8 * 2 + 64 * 65 * 4;
    cudaFuncSetAttribute(lstm_all, cudaFuncAttributeMaxDynamicSharedMemorySize,
                         SMEM_BYTES);

    lstm_all<<<GRID, NTHR, SMEM_BYTES>>>(x, eWih0, eWhh0, eb0, eWih1, eWhh1, eb1,
                                         dWih0, dWhh0, db0, dWih1, dWhh1, db1,
                                         outW, outb, dinit, out);
}

// round 2
// speedup vs baseline: 1.1806x; 1.1806x over previous
#include <cuda_runtime.h>

// ---------------------------------------------------------------------------
// Seq2seq LSTM, persistent kernel, 148 CTAs (1/SM), software grid barrier.
// Round 2: conflict-free smem fragment layouts (LDS.128 at HW-minimum
// wavefronts), cp.async double-buffered K-chunk pipeline, encoder retiled.
// ---------------------------------------------------------------------------

#define HID   256
#define BATCH 256
#define TLEN  512
#define NS    16
#define SBAT  (NS * BATCH)   // 4096
#define HOR   64
#define GRID  148
#define NTHR  256

#define STAGE_BYTES 65536                 // A slot (32KB max) + W slot (32KB)
#define GSM_OFF     (2 * STAGE_BYTES)
#define SMEM_BYTES  (GSM_OFF + 64 * 64 * 4)   // 147456

// ---------------- device scratch (no allocation allowed) -------------------
__device__ float g_eh0[2][BATCH * HID];
__device__ float g_ec0[BATCH * HID];
__device__ float g_eh1[2][BATCH * HID];
__device__ float g_ec1[BATCH * HID];

__device__ float g_dh0[2][SBAT * HID];
__device__ float g_dc0[SBAT * HID];
__device__ float g_dh1[2][SBAT * HID];
__device__ float g_dc1[SBAT * HID];
__device__ float g_dinp[SBAT];

__device__ unsigned g_cnt = 0;
__device__ volatile unsigned g_gen = 0;

// ---------------- grid-wide barrier (all CTAs resident) --------------------
__device__ __forceinline__ void gsync() {
    __syncthreads();
    if (threadIdx.x == 0) {
        __threadfence();
        unsigned old = g_gen;
        unsigned arrived = atomicAdd(&g_cnt, 1u);
        if (arrived == gridDim.x - 1) {
            g_cnt = 0;
            __threadfence();
            g_gen = old + 1u;
        } else {
            while (g_gen == old) { }
            __threadfence();
        }
    }
    __syncthreads();
}

// ---------------- packed f32x2 FMA -----------------------------------------
union F2U { float2 f; unsigned long long u; };

__device__ __forceinline__ float2 ffma2(float2 a, float2 b, float2 c) {
    F2U ua, ub, uc;
    ua.f = a; ub.f = b; uc.f = c;
    asm("fma.rn.f32x2 %0, %1, %2, %0;" : "+l"(uc.u) : "l"(ua.u), "l"(ub.u));
    return uc.f;
}

__device__ __forceinline__ float sigm(float x) {
    return 1.0f / (1.0f + expf(-x));
}

// ---------------- cp.async helpers -----------------------------------------
__device__ __forceinline__ void cpa16(void* dst, const void* src) {
    unsigned d = (unsigned)__cvta_generic_to_shared(dst);
    asm volatile("cp.async.cg.shared.global [%0], [%1], 16;" :: "r"(d), "l"(src));
}
__device__ __forceinline__ void cp_commit() {
    asm volatile("cp.async.commit_group;" ::: "memory");
}
__device__ __forceinline__ void cp_wait0() {
    asm volatile("cp.async.wait_group 0;" ::: "memory");
}
__device__ __forceinline__ void cp_wait1() {
    asm volatile("cp.async.wait_group 1;" ::: "memory");
}

// ---------------------------------------------------------------------------
// Fragment layouts per K-chunk (KC = 128 = 32 k-quads):
//   Af[q * TB + r]             : float4 = A[b0+r][kc+4q .. kc+4q+3]
//   Wf[q * TC + perm(c)]       : float4 = W[row(c)][kc+4q .. kc+4q+3]
//       perm(c) = (c&3)*16 + (c>>2)  -> LDS of lanes 0..15 is 256B contiguous
// Thread map: 16x16 (ty = tid>>4 -> RB rows, tx = tid&15 -> 4 cols).
// ---------------------------------------------------------------------------
template<int TB, int TC>
__device__ __forceinline__ void issue_chunk(
    char* stage, const float* __restrict__ A, const float* __restrict__ W,
    int b0, int j0, int kcol)
{
    constexpr int TJ = TC / 4;
    const int tid = threadIdx.x;
    float4* Af = (float4*)stage;
    float4* Wf = (float4*)(stage + 32768);
#pragma unroll
    for (int i = tid; i < TB * 32; i += NTHR) {
        int r = i >> 5, q = i & 31;
        cpa16(Af + q * TB + r, A + (size_t)(b0 + r) * HID + kcol + q * 4);
    }
#pragma unroll
    for (int i = tid; i < TC * 32; i += NTHR) {
        int c = i >> 5, q = i & 31;
        int gate = c / TJ, jj = c - gate * TJ;
        int slot = (c & 3) * 16 + (c >> 2);
        cpa16(Wf + q * TC + slot,
              W + (size_t)(gate * HID + j0 + jj) * HID + kcol + q * 4);
    }
}

template<int TB, int TC>
__device__ __forceinline__ void compute_chunk(
    const char* stage, float2 (&acc)[TB / 16][4], int ty, int tx)
{
    constexpr int RB = TB / 16;
    const float4* __restrict__ Af = (const float4*)stage;
    const float4* __restrict__ Wf = (const float4*)(stage + 32768);
    const float4* ap = Af + ty * RB;
    const float4* bp = Wf + tx;
#pragma unroll 4
    for (int k4 = 0; k4 < 32; ++k4) {
        float4 a[RB], b[4];
#pragma unroll
        for (int r = 0; r < RB; ++r) a[r] = ap[r];
#pragma unroll
        for (int c = 0; c < 4; ++c) b[c] = bp[c * 16];
#pragma unroll
        for (int r = 0; r < RB; ++r)
#pragma unroll
            for (int c = 0; c < 4; ++c) {
                acc[r][c] = ffma2(make_float2(a[r].x, a[r].y),
                                  make_float2(b[c].x, b[c].y), acc[r][c]);
                acc[r][c] = ffma2(make_float2(a[r].z, a[r].w),
                                  make_float2(b[c].z, b[c].w), acc[r][c]);
            }
        ap += TB;
        bp += TC;
    }
}

// ---------------------------------------------------------------------------
// One [TB x TC] fused LSTM layer-step tile:
//   gates = A1 @ W1^T (+ A2 @ W2^T) (+ inp[b]*wih) + bias, then c/h update.
// K = 256 streamed as 2 chunks per (A,W) pair through a 2-stage cp.async
// pipeline (2 or 4 chunks total).
// ---------------------------------------------------------------------------
template<int TB, int TC>
__device__ __forceinline__ void lstm_tile(
    char* smem, int b0, int j0,
    const float* __restrict__ A1, const float* __restrict__ W1,
    const float* __restrict__ A2, const float* __restrict__ W2,
    const float* __restrict__ inp, int inp_stride,
    const float* __restrict__ wih, const float* __restrict__ bias,
    float* __restrict__ Cst, float* __restrict__ Hout)
{
    constexpr int RB = TB / 16;
    constexpr int TJ = TC / 4;
    const int tid = threadIdx.x;
    const int ty = tid >> 4, tx = tid & 15;
    float* gsm = (float*)(smem + GSM_OFF);

    // per-thread bias / Wih column prefetch (overlaps with loads)
    float bv[4], wv[4];
#pragma unroll
    for (int cc = 0; cc < 4; ++cc) {
        int c = tx * 4 + cc, gate = c / TJ, jj = c - gate * TJ;
        int grow = gate * HID + j0 + jj;
        bv[cc] = bias[grow];
        wv[cc] = wih ? wih[grow] : 0.f;
    }

    const int nch = A2 ? 4 : 2;
    const float* Ac[4] = {A1, A1, A2, A2};
    const float* Wc[4] = {W1, W1, W2, W2};
    const int    kc[4] = {0, 128, 0, 128};

    issue_chunk<TB, TC>(smem, Ac[0], Wc[0], b0, j0, kc[0]);
    cp_commit();
    issue_chunk<TB, TC>(smem + STAGE_BYTES, Ac[1], Wc[1], b0, j0, kc[1]);
    cp_commit();

    float2 acc[RB][4];
#pragma unroll
    for (int r = 0; r < RB; ++r)
#pragma unroll
        for (int c = 0; c < 4; ++c) acc[r][c] = make_float2(0.f, 0.f);

#pragma unroll
    for (int i = 0; i < 4; ++i) {
        if (i >= nch) break;
        if (i + 1 < nch) cp_wait1(); else cp_wait0();
        __syncthreads();
        compute_chunk<TB, TC>(smem + (i & 1) * STAGE_BYTES, acc, ty, tx);
        __syncthreads();
        if (i + 2 < nch) {
            issue_chunk<TB, TC>(smem + (i & 1) * STAGE_BYTES,
                                Ac[i + 2], Wc[i + 2], b0, j0, kc[i + 2]);
            cp_commit();
        }
    }

    // epilogue: pair-sum, + bias + rank-1 input term -> gsm (vector STS.128)
#pragma unroll
    for (int r = 0; r < RB; ++r) {
        int lrow = ty * RB + r;
        float iv = wih ? inp[(size_t)(b0 + lrow) * inp_stride] : 0.f;
        float4 v;
        v.x = acc[r][0].x + acc[r][0].y + bv[0] + iv * wv[0];
        v.y = acc[r][1].x + acc[r][1].y + bv[1] + iv * wv[1];
        v.z = acc[r][2].x + acc[r][2].y + bv[2] + iv * wv[2];
        v.w = acc[r][3].x + acc[r][3].y + bv[3] + iv * wv[3];
        *(float4*)(gsm + lrow * TC + tx * 4) = v;
    }
    __syncthreads();

    // gate update
#pragma unroll
    for (int idx = tid; idx < TB * TJ; idx += NTHR) {
        int lrow = idx / TJ, jj = idx - lrow * TJ;
        const float* gr = gsm + lrow * TC;
        float ig = gr[jj];
        float fg = gr[TJ + jj];
        float gg = gr[2 * TJ + jj];
        float og = gr[3 * TJ + jj];
        int gidx = (b0 + lrow) * HID + (j0 + jj);
        float cn = sigm(fg) * Cst[gidx] + sigm(ig) * tanhf(gg);
        Cst[gidx]  = cn;
        Hout[gidx] = sigm(og) * tanhf(cn);
    }
    __syncthreads();
}

// ---------------------------------------------------------------------------
__global__ void __launch_bounds__(NTHR, 1)
lstm_all(const float* __restrict__ x,
         const float* __restrict__ eWih0, const float* __restrict__ eWhh0,
         const float* __restrict__ eb0,
         const float* __restrict__ eWih1, const float* __restrict__ eWhh1,
         const float* __restrict__ eb1,
         const float* __restrict__ dWih0, const float* __restrict__ dWhh0,
         const float* __restrict__ db0,
         const float* __restrict__ dWih1, const float* __restrict__ dWhh1,
         const float* __restrict__ db1,
         const float* __restrict__ outW, const float* __restrict__ outb,
         const float* __restrict__ dinit,
         float* __restrict__ out)
{
    extern __shared__ char smem[];
    const int tid = threadIdx.x;

    // ---- zero-init encoder state (read buffers = index 0) ----
    for (int i = blockIdx.x * NTHR + tid; i < BATCH * HID; i += GRID * NTHR) {
        g_eh0[0][i] = 0.f; g_ec0[i] = 0.f;
        g_eh1[0][i] = 0.f; g_ec1[i] = 0.f;
    }
    gsync();

    // =========================== encoder ===================================
    // TB=32, TC=64 -> 8 bt x 16 jt = 128 tiles (1 per CTA)
    for (int t = 0; t < TLEN; ++t) {
        const int rp = t & 1, wp = rp ^ 1;
        for (int tile = blockIdx.x; tile < 128; tile += GRID) {
            int bt = tile & 7, jt = tile >> 3;
            lstm_tile<32, 64>(smem, bt * 32, jt * 16,
                              g_eh0[rp], eWhh0, nullptr, nullptr,
                              x + t, TLEN, eWih0, eb0,
                              g_ec0, g_eh0[wp]);
        }
        gsync();
        for (int tile = blockIdx.x; tile < 128; tile += GRID) {
            int bt = tile & 7, jt = tile >> 3;
            lstm_tile<32, 64>(smem, bt * 32, jt * 16,
                              g_eh0[wp], eWih1, g_eh1[rp], eWhh1,
                              nullptr, 0, nullptr, eb1,
                              g_ec1, g_eh1[wp]);
        }
        gsync();
    }

    // ---- decoder init: broadcast final encoder state (buffers index 0) ----
    for (int i = blockIdx.x * NTHR + tid; i < SBAT * HID; i += GRID * NTHR) {
        int b = (i >> 8) & 255;
        int k = i & 255;
        int src = b * HID + k;
        g_dh0[0][i] = g_eh0[0][src];
        g_dc0[i]    = g_ec0[src];
        g_dh1[0][i] = g_eh1[0][src];
        g_dc1[i]    = g_ec1[src];
    }
    for (int i = blockIdx.x * NTHR + tid; i < SBAT; i += GRID * NTHR)
        g_dinp[i] = dinit[i];
    gsync();

    // =========================== decoder ===================================
    // TB=64, TC=64 -> 64 bt x 16 jt = 1024 tiles (~7 per CTA)
    const int warp = tid >> 5, lane = tid & 31;
    for (int t = 0; t < HOR; ++t) {
        const int rp = t & 1, wp = rp ^ 1;
        for (int tile = blockIdx.x; tile < 1024; tile += GRID) {
            int bt = tile & 63, jt = tile >> 6;
            lstm_tile<64, 64>(smem, bt * 64, jt * 16,
                              g_dh0[rp], dWhh0, nullptr, nullptr,
                              g_dinp, 1, dWih0, db0,
                              g_dc0, g_dh0[wp]);
        }
        gsync();
        for (int tile = blockIdx.x; tile < 1024; tile += GRID) {
            int bt = tile & 63, jt = tile >> 6;
            lstm_tile<64, 64>(smem, bt * 64, jt * 16,
                              g_dh0[wp], dWih1, g_dh1[rp], dWhh1,
                              nullptr, 0, nullptr, db1,
                              g_dc1, g_dh1[wp]);
        }
        gsync();
        // ---- pred = h1 @ outW^T + outb ; feeds next step + output ----
        const float* h1w = g_dh1[wp];
        for (int row = blockIdx.x * 8 + warp; row < SBAT; row += GRID * 8) {
            const float* hr = h1w + (size_t)row * HID;
            float s = 0.f;
#pragma unroll
            for (int kb = 0; kb < 2; ++kb) {
                int kk = kb * 128 + lane * 4;
                float4 hv = *reinterpret_cast<const float4*>(hr + kk);
                float4 wv = *reinterpret_cast<const float4*>(outW + kk);
                s += hv.x * wv.x + hv.y * wv.y + hv.z * wv.z + hv.w * wv.w;
            }
#pragma unroll
            for (int off = 16; off; off >>= 1)
                s += __shfl_xor_sync(0xffffffffu, s, off);
            if (lane == 0) {
                float p = s + outb[0];
                g_dinp[row] = p;
                int b = row & 255, sidx = row >> 8;
                out[(size_t)b * (NS * HOR) + sidx * HOR + t] = p;
            }
        }
        gsync();
    }
}

// ---------------------------------------------------------------------------
extern "C" void kernel_launch(void* const* d_in, const int* in_sizes, int n_in,
                              void* d_out, int out_size)
{
    (void)in_sizes; (void)n_in; (void)out_size;
    const float* x     = (const float*)d_in[0];
    const float* eWih0 = (const float*)d_in[1];
    const float* eWhh0 = (const float*)d_in[2];
    const float* eb0   = (const float*)d_in[3];
    const float* eWih1 = (const float*)d_in[4];
    const float* eWhh1 = (const float*)d_in[5];
    const float* eb1   = (const float*)d_in[6];
    const float* dWih0 = (const float*)d_in[7];
    const float* dWhh0 = (const float*)d_in[8];
    const float* db0   = (const float*)d_in[9];
    const float* dWih1 = (const float*)d_in[10];
    const float* dWhh1 = (const float*)d_in[11];
    const float* db1   = (const float*)d_in[12];
    const float* outW  = (const float*)d_in[13];
    const float* outb  = (const float*)d_in[14];
    const float* dinit = (const float*)d_in[15];
    float* out = (float*)d_out;

    cudaFuncSetAttribute(lstm_all, cudaFuncAttributeMaxDynamicSharedMemorySize,
                         SMEM_BYTES);

    lstm_all<<<GRID, NTHR, SMEM_BYTES>>>(x, eWih0, eWhh0, eb0, eWih1, eWhh1, eb1,
                                         dWih0, dWhh0, db0, dWih1, dWhh1, db1,
                                         outW, outb, dinit, out);
}

// round 3
// speedup vs baseline: 1.1837x; 1.0026x over previous
#include <cuda_runtime.h>

// ---------------------------------------------------------------------------
// Seq2seq LSTM, persistent kernel, 148 CTAs (1/SM), software grid barrier.
// Round 2: conflict-free smem fragment layouts (LDS.128 at HW-minimum
// wavefronts), cp.async double-buffered K-chunk pipeline, encoder retiled.
// ---------------------------------------------------------------------------

#define HID   256
#define BATCH 256
#define TLEN  512
#define NS    16
#define SBAT  (NS * BATCH)   // 4096
#define HOR   64
#define GRID  148
#define NTHR  256

#define STAGE_BYTES 65536                 // A slot (32KB max) + W slot (32KB)
#define GSM_OFF     (2 * STAGE_BYTES)
#define SMEM_BYTES  (GSM_OFF + 64 * 64 * 4)   // 147456

// ---------------- device scratch (no allocation allowed) -------------------
__device__ float g_eh0[2][BATCH * HID];
__device__ float g_ec0[BATCH * HID];
__device__ float g_eh1[2][BATCH * HID];
__device__ float g_ec1[BATCH * HID];

__device__ float g_dh0[2][SBAT * HID];
__device__ float g_dc0[SBAT * HID];
__device__ float g_dh1[2][SBAT * HID];
__device__ float g_dc1[SBAT * HID];
__device__ float g_dinp[SBAT];

__device__ unsigned g_cnt = 0;
__device__ volatile unsigned g_gen = 0;

// ---------------- grid-wide barrier (all CTAs resident) --------------------
__device__ __forceinline__ void gsync() {
    __syncthreads();
    if (threadIdx.x == 0) {
        __threadfence();
        unsigned old = g_gen;
        unsigned arrived = atomicAdd(&g_cnt, 1u);
        if (arrived == gridDim.x - 1) {
            g_cnt = 0;
            __threadfence();
            g_gen = old + 1u;
        } else {
            while (g_gen == old) { }
            __threadfence();
        }
    }
    __syncthreads();
}

// ---------------- packed f32x2 FMA -----------------------------------------
union F2U { float2 f; unsigned long long u; };

__device__ __forceinline__ float2 ffma2(float2 a, float2 b, float2 c) {
    F2U ua, ub, uc;
    ua.f = a; ub.f = b; uc.f = c;
    asm("fma.rn.f32x2 %0, %1, %2, %0;" : "+l"(uc.u) : "l"(ua.u), "l"(ub.u));
    return uc.f;
}

__device__ __forceinline__ float sigm(float x) {
    return 1.0f / (1.0f + expf(-x));
}

// ---------------- cp.async helpers -----------------------------------------
__device__ __forceinline__ void cpa16(void* dst, const void* src) {
    unsigned d = (unsigned)__cvta_generic_to_shared(dst);
    asm volatile("cp.async.cg.shared.global [%0], [%1], 16;" :: "r"(d), "l"(src));
}
__device__ __forceinline__ void cp_commit() {
    asm volatile("cp.async.commit_group;" ::: "memory");
}
__device__ __forceinline__ void cp_wait0() {
    asm volatile("cp.async.wait_group 0;" ::: "memory");
}
__device__ __forceinline__ void cp_wait1() {
    asm volatile("cp.async.wait_group 1;" ::: "memory");
}

// ---------------------------------------------------------------------------
// Fragment layouts per K-chunk (KC = 128 = 32 k-quads):
//   Af[q * TB + r]             : float4 = A[b0+r][kc+4q .. kc+4q+3]
//   Wf[q * TC + perm(c)]       : float4 = W[row(c)][kc+4q .. kc+4q+3]
//       perm(c) = (c&3)*16 + (c>>2)  -> LDS of lanes 0..15 is 256B contiguous
// Thread map: 16x16 (ty = tid>>4 -> RB rows, tx = tid&15 -> 4 cols).
// ---------------------------------------------------------------------------
template<int TB, int TC>
__device__ __forceinline__ void issue_chunk(
    char* stage, const float* __restrict__ A, const float* __restrict__ W,
    int b0, int j0, int kcol)
{
    constexpr int TJ = TC / 4;
    const int tid = threadIdx.x;
    float4* Af = (float4*)stage;
    float4* Wf = (float4*)(stage + 32768);
#pragma unroll
    for (int i = tid; i < TB * 32; i += NTHR) {
        int r = i >> 5, q = i & 31;
        cpa16(Af + q * TB + r, A + (size_t)(b0 + r) * HID + kcol + q * 4);
    }
#pragma unroll
    for (int i = tid; i < TC * 32; i += NTHR) {
        int c = i >> 5, q = i & 31;
        int gate = c / TJ, jj = c - gate * TJ;
        int slot = (c & 3) * 16 + (c >> 2);
        cpa16(Wf + q * TC + slot,
              W + (size_t)(gate * HID + j0 + jj) * HID + kcol + q * 4);
    }
}

template<int TB, int TC>
__device__ __forceinline__ void compute_chunk(
    const char* stage, float2 (&acc)[TB / 16][4], int ty, int tx)
{
    constexpr int RB = TB / 16;
    const float4* __restrict__ Af = (const float4*)stage;
    const float4* __restrict__ Wf = (const float4*)(stage + 32768);
    const float4* ap = Af + ty * RB;
    const float4* bp = Wf + tx;
#pragma unroll 4
    for (int k4 = 0; k4 < 32; ++k4) {
        float4 a[RB], b[4];
#pragma unroll
        for (int r = 0; r < RB; ++r) a[r] = ap[r];
#pragma unroll
        for (int c = 0; c < 4; ++c) b[c] = bp[c * 16];
#pragma unroll
        for (int r = 0; r < RB; ++r)
#pragma unroll
            for (int c = 0; c < 4; ++c) {
                acc[r][c] = ffma2(make_float2(a[r].x, a[r].y),
                                  make_float2(b[c].x, b[c].y), acc[r][c]);
                acc[r][c] = ffma2(make_float2(a[r].z, a[r].w),
                                  make_float2(b[c].z, b[c].w), acc[r][c]);
            }
        ap += TB;
        bp += TC;
    }
}

// ---------------------------------------------------------------------------
// One [TB x TC] fused LSTM layer-step tile:
//   gates = A1 @ W1^T (+ A2 @ W2^T) (+ inp[b]*wih) + bias, then c/h update.
// K = 256 streamed as 2 chunks per (A,W) pair through a 2-stage cp.async
// pipeline (2 or 4 chunks total).
// ---------------------------------------------------------------------------
template<int TB, int TC>
__device__ __forceinline__ void lstm_tile(
    char* smem, int b0, int j0,
    const float* __restrict__ A1, const float* __restrict__ W1,
    const float* __restrict__ A2, const float* __restrict__ W2,
    const float* __restrict__ inp, int inp_stride,
    const float* __restrict__ wih, const float* __restrict__ bias,
    float* __restrict__ Cst, float* __restrict__ Hout)
{
    constexpr int RB = TB / 16;
    constexpr int TJ = TC / 4;
    const int tid = threadIdx.x;
    const int ty = tid >> 4, tx = tid & 15;
    float* gsm = (float*)(smem + GSM_OFF);

    // per-thread bias / Wih column prefetch (overlaps with loads)
    float bv[4], wv[4];
#pragma unroll
    for (int cc = 0; cc < 4; ++cc) {
        int c = tx * 4 + cc, gate = c / TJ, jj = c - gate * TJ;
        int grow = gate * HID + j0 + jj;
        bv[cc] = bias[grow];
        wv[cc] = wih ? wih[grow] : 0.f;
    }

    const int nch = A2 ? 4 : 2;
    const float* Ac[4] = {A1, A1, A2, A2};
    const float* Wc[4] = {W1, W1, W2, W2};
    const int    kc[4] = {0, 128, 0, 128};

    issue_chunk<TB, TC>(smem, Ac[0], Wc[0], b0, j0, kc[0]);
    cp_commit();
    issue_chunk<TB, TC>(smem + STAGE_BYTES, Ac[1], Wc[1], b0, j0, kc[1]);
    cp_commit();

    float2 acc[RB][4];
#pragma unroll
    for (int r = 0; r < RB; ++r)
#pragma unroll
        for (int c = 0; c < 4; ++c) acc[r][c] = make_float2(0.f, 0.f);

#pragma unroll
    for (int i = 0; i < 4; ++i) {
        if (i >= nch) break;
        if (i + 1 < nch) cp_wait1(); else cp_wait0();
        __syncthreads();
        compute_chunk<TB, TC>(smem + (i & 1) * STAGE_BYTES, acc, ty, tx);
        __syncthreads();
        if (i + 2 < nch) {
            issue_chunk<TB, TC>(smem + (i & 1) * STAGE_BYTES,
                                Ac[i + 2], Wc[i + 2], b0, j0, kc[i + 2]);
            cp_commit();
        }
    }

    // epilogue: pair-sum, + bias + rank-1 input term -> gsm (vector STS.128)
#pragma unroll
    for (int r = 0; r < RB; ++r) {
        int lrow = ty * RB + r;
        float iv = wih ? inp[(size_t)(b0 + lrow) * inp_stride] : 0.f;
        float4 v;
        v.x = acc[r][0].x + acc[r][0].y + bv[0] + iv * wv[0];
        v.y = acc[r][1].x + acc[r][1].y + bv[1] + iv * wv[1];
        v.z = acc[r][2].x + acc[r][2].y + bv[2] + iv * wv[2];
        v.w = acc[r][3].x + acc[r][3].y + bv[3] + iv * wv[3];
        *(float4*)(gsm + lrow * TC + tx * 4) = v;
    }
    __syncthreads();

    // gate update
#pragma unroll
    for (int idx = tid; idx < TB * TJ; idx += NTHR) {
        int lrow = idx / TJ, jj = idx - lrow * TJ;
        const float* gr = gsm + lrow * TC;
        float ig = gr[jj];
        float fg = gr[TJ + jj];
        float gg = gr[2 * TJ + jj];
        float og = gr[3 * TJ + jj];
        int gidx = (b0 + lrow) * HID + (j0 + jj);
        float cn = sigm(fg) * Cst[gidx] + sigm(ig) * tanhf(gg);
        Cst[gidx]  = cn;
        Hout[gidx] = sigm(og) * tanhf(cn);
    }
    __syncthreads();
}

// ---------------------------------------------------------------------------
__global__ void __launch_bounds__(NTHR, 1)
lstm_all(const float* __restrict__ x,
         const float* __restrict__ eWih0, const float* __restrict__ eWhh0,
         const float* __restrict__ eb0,
         const float* __restrict__ eWih1, const float* __restrict__ eWhh1,
         const float* __restrict__ eb1,
         const float* __restrict__ dWih0, const float* __restrict__ dWhh0,
         const float* __restrict__ db0,
         const float* __restrict__ dWih1, const float* __restrict__ dWhh1,
         const float* __restrict__ db1,
         const float* __restrict__ outW, const float* __restrict__ outb,
         const float* __restrict__ dinit,
         float* __restrict__ out)
{
    extern __shared__ char smem[];
    const int tid = threadIdx.x;

    // ---- zero-init encoder state (read buffers = index 0) ----
    for (int i = blockIdx.x * NTHR + tid; i < BATCH * HID; i += GRID * NTHR) {
        g_eh0[0][i] = 0.f; g_ec0[i] = 0.f;
        g_eh1[0][i] = 0.f; g_ec1[i] = 0.f;
    }
    gsync();

    // =========================== encoder ===================================
    // TB=32, TC=64 -> 8 bt x 16 jt = 128 tiles (1 per CTA)
    for (int t = 0; t < TLEN; ++t) {
        const int rp = t & 1, wp = rp ^ 1;
        for (int tile = blockIdx.x; tile < 128; tile += GRID) {
            int bt = tile & 7, jt = tile >> 3;
            lstm_tile<32, 64>(smem, bt * 32, jt * 16,
                              g_eh0[rp], eWhh0, nullptr, nullptr,
                              x + t, TLEN, eWih0, eb0,
                              g_ec0, g_eh0[wp]);
        }
        gsync();
        for (int tile = blockIdx.x; tile < 128; tile += GRID) {
            int bt = tile & 7, jt = tile >> 3;
            lstm_tile<32, 64>(smem, bt * 32, jt * 16,
                              g_eh0[wp], eWih1, g_eh1[rp], eWhh1,
                              nullptr, 0, nullptr, eb1,
                              g_ec1, g_eh1[wp]);
        }
        gsync();
    }

    // ---- decoder init: broadcast final encoder state (buffers index 0) ----
    for (int i = blockIdx.x * NTHR + tid; i < SBAT * HID; i += GRID * NTHR) {
        int b = (i >> 8) & 255;
        int k = i & 255;
        int src = b * HID + k;
        g_dh0[0][i] = g_eh0[0][src];
        g_dc0[i]    = g_ec0[src];
        g_dh1[0][i] = g_eh1[0][src];
        g_dc1[i]    = g_ec1[src];
    }
    for (int i = blockIdx.x * NTHR + tid; i < SBAT; i += GRID * NTHR)
        g_dinp[i] = dinit[i];
    gsync();

    // =========================== decoder ===================================
    // TB=64, TC=64 -> 64 bt x 16 jt = 1024 tiles (~7 per CTA)
    const int warp = tid >> 5, lane = tid & 31;
    for (int t = 0; t < HOR; ++t) {
        const int rp = t & 1, wp = rp ^ 1;
        for (int tile = blockIdx.x; tile < 1024; tile += GRID) {
            int bt = tile & 63, jt = tile >> 6;
            lstm_tile<64, 64>(smem, bt * 64, jt * 16,
                              g_dh0[rp], dWhh0, nullptr, nullptr,
                              g_dinp, 1, dWih0, db0,
                              g_dc0, g_dh0[wp]);
        }
        gsync();
        for (int tile = blockIdx.x; tile < 1024; tile += GRID) {
            int bt = tile & 63, jt = tile >> 6;
            lstm_tile<64, 64>(smem, bt * 64, jt * 16,
                              g_dh0[wp], dWih1, g_dh1[rp], dWhh1,
                              nullptr, 0, nullptr, db1,
                              g_dc1, g_dh1[wp]);
        }
        gsync();
        // ---- pred = h1 @ outW^T + outb ; feeds next step + output ----
        const float* h1w = g_dh1[wp];
        for (int row = blockIdx.x * 8 + warp; row < SBAT; row += GRID * 8) {
            const float* hr = h1w + (size_t)row * HID;
            float s = 0.f;
#pragma unroll
            for (int kb = 0; kb < 2; ++kb) {
                int kk = kb * 128 + lane * 4;
                float4 hv = *reinterpret_cast<const float4*>(hr + kk);
                float4 wv = *reinterpret_cast<const float4*>(outW + kk);
                s += hv.x * wv.x + hv.y * wv.y + hv.z * wv.z + hv.w * wv.w;
            }
#pragma unroll
            for (int off = 16; off; off >>= 1)
                s += __shfl_xor_sync(0xffffffffu, s, off);
            if (lane == 0) {
                float p = s + outb[0];
                g_dinp[row] = p;
                int b = row & 255, sidx = row >> 8;
                out[(size_t)b * (NS * HOR) + sidx * HOR + t] = p;
            }
        }
        gsync();
    }
}

// ---------------------------------------------------------------------------
extern "C" void kernel_launch(void* const* d_in, const int* in_sizes, int n_in,
                              void* d_out, int out_size)
{
    (void)in_sizes; (void)n_in; (void)out_size;
    const float* x     = (const float*)d_in[0];
    const float* eWih0 = (const float*)d_in[1];
    const float* eWhh0 = (const float*)d_in[2];
    const float* eb0   = (const float*)d_in[3];
    const float* eWih1 = (const float*)d_in[4];
    const float* eWhh1 = (const float*)d_in[5];
    const float* eb1   = (const float*)d_in[6];
    const float* dWih0 = (const float*)d_in[7];
    const float* dWhh0 = (const float*)d_in[8];
    const float* db0   = (const float*)d_in[9];
    const float* dWih1 = (const float*)d_in[10];
    const float* dWhh1 = (const float*)d_in[11];
    const float* db1   = (const float*)d_in[12];
    const float* outW  = (const float*)d_in[13];
    const float* outb  = (const float*)d_in[14];
    const float* dinit = (const float*)d_in[15];
    float* out = (float*)d_out;

    cudaFuncSetAttribute(lstm_all, cudaFuncAttributeMaxDynamicSharedMemorySize,
                         SMEM_BYTES);

    lstm_all<<<GRID, NTHR, SMEM_BYTES>>>(x, eWih0, eWhh0, eb0, eWih1, eWhh1, eb1,
                                         dWih0, dWhh0, db0, dWih1, dWhh1, db1,
                                         outW, outb, dinit, out);
}